// round 5
// baseline (speedup 1.0000x reference)
#include <cuda_runtime.h>

#define E_EDGE 8192
#define BATCH  32
#define N_VAR  2048
#define DEPTH  8
#define NCHUNK (E_EDGE / 128)   // 64 chunks of 128 floats (512B) per row

// scratch: input transposed to [k][b] (1 MB) and llr pre-scaled+transposed to [v][b] (256 KB)
__device__ float g_inputT[E_EDGE * BATCH];
__device__ float g_llrT[N_VAR * BATCH];

__global__ __launch_bounds__(256) void prep_kernel(const float* __restrict__ input,
                                                   const float* __restrict__ llr,
                                                   const float* __restrict__ llr_w) {
    int tid = blockIdx.x * blockDim.x + threadIdx.x;
    if (tid < E_EDGE * BATCH) {
        int b = tid >> 13;           // tid / 8192  (coalesced read along k)
        int k = tid & (E_EDGE - 1);
        g_inputT[k * BATCH + b] = input[tid];
    } else {
        int t = tid - E_EDGE * BATCH;
        if (t < N_VAR * BATCH) {
            int b = t >> 11;         // t / 2048
            int v = t & (N_VAR - 1);
            g_llrT[v * BATCH + b] = llr[t] * llr_w[v];
        }
    }
}

// One warp per output row e_out; lane = batch b.
// Mask (the only streamed matrix) flows through an 8-deep cp.async ring in smem:
// MLP is held by the async-copy engine, not registers, so occupancy stays high
// AND each warp keeps 4KB in flight. Weight is gathered pointwise only at mask
// nonzeros (mask*weight == 0 wherever mask == 0, for any weight values).
__global__ __launch_bounds__(256) void bp_main_kernel(
    const float* __restrict__ mask,
    const float* __restrict__ weight,
    float* __restrict__ out)
{
    __shared__ float4 buf[8][DEPTH][32];   // [warp][stage][lane] = 32 KB
    __shared__ float tile[8][33];

    const int warp = threadIdx.x >> 5;          // 0..7
    const int lane = threadIdx.x & 31;          // batch b
    const int row0 = blockIdx.x << 3;           // 8 rows per block
    const int row  = row0 + warp;               // e_out

    const float4* __restrict__ m4 = reinterpret_cast<const float4*>(mask + (size_t)row * E_EDGE);
    const float*  __restrict__ wr = weight + (size_t)row * E_EDGE;

    float acc = 0.0f;

    // ── prologue: fill the 8-stage ring ──────────────────────────────────
    #pragma unroll
    for (int s = 0; s < DEPTH; ++s) {
        unsigned saddr = (unsigned)__cvta_generic_to_shared(&buf[warp][s][lane]);
        const float4* gp = &m4[s * 32 + lane];
        asm volatile("cp.async.cg.shared.global [%0], [%1], 16;\n" :: "r"(saddr), "l"(gp) : "memory");
        asm volatile("cp.async.commit_group;\n" ::: "memory");
    }

    // ── steady state ─────────────────────────────────────────────────────
    for (int it = 0; it < NCHUNK; ++it) {
        asm volatile("cp.async.wait_group 7;\n" ::: "memory");

        const int st = it & (DEPTH - 1);
        unsigned saddr = (unsigned)__cvta_generic_to_shared(&buf[warp][st][lane]);
        float4 m;
        asm volatile("ld.shared.v4.f32 {%0,%1,%2,%3}, [%4];"
                     : "=f"(m.x), "=f"(m.y), "=f"(m.z), "=f"(m.w) : "r"(saddr));

        // refill this slot for chunk it+DEPTH. Always commit (empty groups past
        // the end) so the pending-group count stays at 8 and wait_group 7 is
        // exactly "chunk it complete".
        const int nxt = it + DEPTH;
        if (nxt < NCHUNK) {
            const float4* gp = &m4[nxt * 32 + lane];
            asm volatile("cp.async.cg.shared.global [%0], [%1], 16;\n" :: "r"(saddr), "l"(gp) : "memory");
        }
        asm volatile("cp.async.commit_group;\n" ::: "memory");

        bool nz = (m.x != 0.0f) | (m.y != 0.0f) | (m.z != 0.0f) | (m.w != 0.0f);
        unsigned ball = __ballot_sync(0xFFFFFFFFu, nz);

        // rare path: ~8 nonzeros per whole row of 8192
        while (ball) {
            int src = __ffs(ball) - 1;
            ball &= ball - 1;
            float mx = __shfl_sync(0xFFFFFFFFu, m.x, src);
            float my = __shfl_sync(0xFFFFFFFFu, m.y, src);
            float mz = __shfl_sync(0xFFFFFFFFu, m.z, src);
            float mw = __shfl_sync(0xFFFFFFFFu, m.w, src);
            const int k0 = it * 128 + src * 4;
            const float* t = g_inputT + (size_t)k0 * BATCH + lane;  // coalesced
            if (mx != 0.0f) acc = fmaf(mx * __ldg(&wr[k0 + 0]), t[0 * BATCH], acc);
            if (my != 0.0f) acc = fmaf(my * __ldg(&wr[k0 + 1]), t[1 * BATCH], acc);
            if (mz != 0.0f) acc = fmaf(mz * __ldg(&wr[k0 + 2]), t[2 * BATCH], acc);
            if (mw != 0.0f) acc = fmaf(mw * __ldg(&wr[k0 + 3]), t[3 * BATCH], acc);
        }
    }

    // epilogue: llr term (pre-scaled, coalesced) + smem transpose for full-sector stores
    const int v = row & (N_VAR - 1);
    const float l = g_llrT[v * BATCH + lane];
    tile[warp][lane] = 0.5f * (l + acc);
    __syncthreads();

    // thread t: b = t>>3 (0..31), e_local = t&7 -> each 8-thread group writes one
    // full, aligned 32B sector of out[b][row0 .. row0+7]
    const int b  = threadIdx.x >> 3;
    const int el = threadIdx.x & 7;
    out[(size_t)b * E_EDGE + row0 + el] = tile[el][b];
}

extern "C" void kernel_launch(void* const* d_in, const int* in_sizes, int n_in,
                              void* d_out, int out_size) {
    const float* input    = (const float*)d_in[0];  // [32, 8192]
    const float* input_w  = (const float*)d_in[1];  // [8192, 8192]
    const float* mask     = (const float*)d_in[2];  // [8192, 8192]
    const float* llr      = (const float*)d_in[3];  // [32, 2048]
    const float* llr_w    = (const float*)d_in[4];  // [1, 2048]
    // d_in[5] = llr_expander (one-hot of e % N_VAR) — realized via index math
    float* out = (float*)d_out;                     // [32, 8192]

    (void)in_sizes; (void)n_in; (void)out_size;

    const int prep_n = E_EDGE * BATCH + N_VAR * BATCH;
    prep_kernel<<<(prep_n + 255) / 256, 256>>>(input, llr, llr_w);

    // 8192 rows, 8 rows (warps) per 256-thread block
    bp_main_kernel<<<E_EDGE / 8, 256>>>(mask, input_w, out);
}

// round 7
// speedup vs baseline: 1.0618x; 1.0618x over previous
#include <cuda_runtime.h>

#define E_EDGE 8192
#define BATCH  32
#define N_VAR  2048

// scratch: input transposed to [k][b] (1 MB) and llr pre-scaled+transposed to [v][b] (256 KB)
__device__ float g_inputT[E_EDGE * BATCH];
__device__ float g_llrT[N_VAR * BATCH];

__global__ __launch_bounds__(256) void prep_kernel(const float* __restrict__ input,
                                                   const float* __restrict__ llr,
                                                   const float* __restrict__ llr_w) {
    int tid = blockIdx.x * blockDim.x + threadIdx.x;
    if (tid < E_EDGE * BATCH) {
        int b = tid >> 13;           // tid / 8192  (coalesced read along k)
        int k = tid & (E_EDGE - 1);
        g_inputT[k * BATCH + b] = input[tid];
    } else {
        int t = tid - E_EDGE * BATCH;
        if (t < N_VAR * BATCH) {
            int b = t >> 11;         // t / 2048
            int v = t & (N_VAR - 1);
            g_llrT[v * BATCH + b] = llr[t] * llr_w[v];
        }
    }
}

// One warp per output row e_out; lane = batch b.
// Only the mask is streamed (256 MB): mask*weight == 0 wherever mask == 0 for
// ANY weight, so weight is gathered pointwise at mask nonzeros only.
// Register double-buffer: group g+1's 4 chunks are prefetched BEFORE group g's
// ballots run, so each warp keeps 2KB in flight continuously (no inter-group
// stall like R4's single-buffer batch).
__global__ __launch_bounds__(256, 5) void bp_main_kernel(
    const float* __restrict__ mask,
    const float* __restrict__ weight,
    float* __restrict__ out)
{
    const int warp = threadIdx.x >> 5;          // 0..7
    const int lane = threadIdx.x & 31;          // batch b
    const int row0 = blockIdx.x << 3;           // 8 rows per block
    const int row  = row0 + warp;               // e_out

    const float4* __restrict__ m4 = reinterpret_cast<const float4*>(mask + (size_t)row * E_EDGE);
    const float*  __restrict__ wr = weight + (size_t)row * E_EDGE;

    float acc = 0.0f;

    float4 cur[4], nxt[4];
    #pragma unroll
    for (int it = 0; it < 4; ++it) cur[it] = __ldcs(&m4[it * 32 + lane]);

    const int NG = E_EDGE / 512;                // 16 groups of 4 chunks
    for (int g = 0; g < NG; ++g) {
        // prefetch next group first — independent of this group's processing
        if (g + 1 < NG) {
            #pragma unroll
            for (int it = 0; it < 4; ++it)
                nxt[it] = __ldcs(&m4[((g + 1) * 4 + it) * 32 + lane]);
        }

        #pragma unroll
        for (int it = 0; it < 4; ++it) {
            // integer nz test; <<1 drops the sign bit so ±0.0 is skipped (exact)
            unsigned bits = (__float_as_uint(cur[it].x) | __float_as_uint(cur[it].y) |
                             __float_as_uint(cur[it].z) | __float_as_uint(cur[it].w)) << 1;
            unsigned ball = __ballot_sync(0xFFFFFFFFu, bits != 0u);

            // rare path: ~8 nonzeros per whole row of 8192
            while (ball) {
                int src = __ffs(ball) - 1;
                ball &= ball - 1;
                float mx = __shfl_sync(0xFFFFFFFFu, cur[it].x, src);
                float my = __shfl_sync(0xFFFFFFFFu, cur[it].y, src);
                float mz = __shfl_sync(0xFFFFFFFFu, cur[it].z, src);
                float mw = __shfl_sync(0xFFFFFFFFu, cur[it].w, src);
                const int k0 = (g * 4 + it) * 128 + src * 4;
                const float* t = g_inputT + (size_t)k0 * BATCH + lane;  // coalesced
                if (mx != 0.0f) acc = fmaf(mx * __ldg(&wr[k0 + 0]), t[0 * BATCH], acc);
                if (my != 0.0f) acc = fmaf(my * __ldg(&wr[k0 + 1]), t[1 * BATCH], acc);
                if (mz != 0.0f) acc = fmaf(mz * __ldg(&wr[k0 + 2]), t[2 * BATCH], acc);
                if (mw != 0.0f) acc = fmaf(mw * __ldg(&wr[k0 + 3]), t[3 * BATCH], acc);
            }
        }

        #pragma unroll
        for (int it = 0; it < 4; ++it) cur[it] = nxt[it];
    }

    // epilogue: llr term (pre-scaled, coalesced) + smem transpose for full-sector stores
    __shared__ float tile[8][33];
    const int v = row & (N_VAR - 1);
    const float l = g_llrT[v * BATCH + lane];
    tile[warp][lane] = 0.5f * (l + acc);
    __syncthreads();

    // thread t: b = t>>3 (0..31), e_local = t&7 -> each 8-thread group writes one
    // full, aligned 32B sector of out[b][row0 .. row0+7]
    const int b  = threadIdx.x >> 3;
    const int el = threadIdx.x & 7;
    out[(size_t)b * E_EDGE + row0 + el] = tile[el][b];
}

extern "C" void kernel_launch(void* const* d_in, const int* in_sizes, int n_in,
                              void* d_out, int out_size) {
    const float* input    = (const float*)d_in[0];  // [32, 8192]
    const float* input_w  = (const float*)d_in[1];  // [8192, 8192]
    const float* mask     = (const float*)d_in[2];  // [8192, 8192]
    const float* llr      = (const float*)d_in[3];  // [32, 2048]
    const float* llr_w    = (const float*)d_in[4];  // [1, 2048]
    // d_in[5] = llr_expander (one-hot of e % N_VAR) — realized via index math
    float* out = (float*)d_out;                     // [32, 8192]

    (void)in_sizes; (void)n_in; (void)out_size;

    const int prep_n = E_EDGE * BATCH + N_VAR * BATCH;
    prep_kernel<<<(prep_n + 255) / 256, 256>>>(input, llr, llr_w);

    // 8192 rows, 8 rows (warps) per 256-thread block
    bp_main_kernel<<<E_EDGE / 8, 256>>>(mask, input_w, out);
}

// round 8
// speedup vs baseline: 1.2407x; 1.1684x over previous
#include <cuda_runtime.h>

#define E_EDGE 8192
#define BATCH  32
#define N_VAR  2048

// scratch: input transposed to [k][b] (1 MB) and llr pre-scaled+transposed to [v][b] (256 KB)
__device__ float g_inputT[E_EDGE * BATCH];
__device__ float g_llrT[N_VAR * BATCH];

__global__ __launch_bounds__(256) void prep_kernel(const float* __restrict__ input,
                                                   const float* __restrict__ llr,
                                                   const float* __restrict__ llr_w) {
    int tid = blockIdx.x * blockDim.x + threadIdx.x;
    if (tid < E_EDGE * BATCH) {
        int b = tid >> 13;           // tid / 8192  (coalesced read along k)
        int k = tid & (E_EDGE - 1);
        g_inputT[k * BATCH + b] = input[tid];
    } else {
        int t = tid - E_EDGE * BATCH;
        if (t < N_VAR * BATCH) {
            int b = t >> 11;         // t / 2048
            int v = t & (N_VAR - 1);
            g_llrT[v * BATCH + b] = llr[t] * llr_w[v];
        }
    }
}

// One warp per TWO output rows (rowA, rowB = rowA+8); lane = batch b.
// This replicates R3's winning memory pattern (8 independent 128B loads issued
// back-to-back per group, default launch bounds, high occupancy) but both load
// streams are mask rows — the weight matrix is never streamed (mask*weight == 0
// wherever mask == 0, for any weight; weight is gathered only at nonzeros).
__global__ __launch_bounds__(256) void bp_main_kernel(
    const float* __restrict__ mask,
    const float* __restrict__ weight,
    float* __restrict__ out)
{
    const int warp = threadIdx.x >> 5;          // 0..7
    const int lane = threadIdx.x & 31;          // batch b
    const int row0 = blockIdx.x << 4;           // 16 rows per block
    const int rowA = row0 + warp;
    const int rowB = rowA + 8;

    const float4* __restrict__ a4 = reinterpret_cast<const float4*>(mask + (size_t)rowA * E_EDGE);
    const float4* __restrict__ b4 = reinterpret_cast<const float4*>(mask + (size_t)rowB * E_EDGE);
    const float*  __restrict__ wa = weight + (size_t)rowA * E_EDGE;
    const float*  __restrict__ wb = weight + (size_t)rowB * E_EDGE;

    float accA = 0.0f, accB = 0.0f;

    // 16 groups × (4 chunks × 2 rows × 128B) = full 8192-wide rows for both
    for (int g = 0; g < E_EDGE / 512; ++g) {
        float4 ma[4], mb[4];
        // 8 independent loads, issued back-to-back (the R3 pattern)
        #pragma unroll
        for (int it = 0; it < 4; ++it) ma[it] = __ldcs(&a4[(g * 4 + it) * 32 + lane]);
        #pragma unroll
        for (int it = 0; it < 4; ++it) mb[it] = __ldcs(&b4[(g * 4 + it) * 32 + lane]);

        #pragma unroll
        for (int it = 0; it < 4; ++it) {
            const int k0base = (g * 4 + it) * 128;
            // integer nz test; <<1 drops sign bit so ±0.0 is skipped (exact)
            unsigned bitsA = (__float_as_uint(ma[it].x) | __float_as_uint(ma[it].y) |
                              __float_as_uint(ma[it].z) | __float_as_uint(ma[it].w)) << 1;
            unsigned bitsB = (__float_as_uint(mb[it].x) | __float_as_uint(mb[it].y) |
                              __float_as_uint(mb[it].z) | __float_as_uint(mb[it].w)) << 1;
            unsigned ballA = __ballot_sync(0xFFFFFFFFu, bitsA != 0u);
            unsigned ballB = __ballot_sync(0xFFFFFFFFu, bitsB != 0u);

            while (ballA) {
                int src = __ffs(ballA) - 1;
                ballA &= ballA - 1;
                float mx = __shfl_sync(0xFFFFFFFFu, ma[it].x, src);
                float my = __shfl_sync(0xFFFFFFFFu, ma[it].y, src);
                float mz = __shfl_sync(0xFFFFFFFFu, ma[it].z, src);
                float mw = __shfl_sync(0xFFFFFFFFu, ma[it].w, src);
                const int k0 = k0base + src * 4;
                const float* t = g_inputT + (size_t)k0 * BATCH + lane;
                if (mx != 0.0f) accA = fmaf(mx * __ldg(&wa[k0 + 0]), t[0 * BATCH], accA);
                if (my != 0.0f) accA = fmaf(my * __ldg(&wa[k0 + 1]), t[1 * BATCH], accA);
                if (mz != 0.0f) accA = fmaf(mz * __ldg(&wa[k0 + 2]), t[2 * BATCH], accA);
                if (mw != 0.0f) accA = fmaf(mw * __ldg(&wa[k0 + 3]), t[3 * BATCH], accA);
            }
            while (ballB) {
                int src = __ffs(ballB) - 1;
                ballB &= ballB - 1;
                float mx = __shfl_sync(0xFFFFFFFFu, mb[it].x, src);
                float my = __shfl_sync(0xFFFFFFFFu, mb[it].y, src);
                float mz = __shfl_sync(0xFFFFFFFFu, mb[it].z, src);
                float mw = __shfl_sync(0xFFFFFFFFu, mb[it].w, src);
                const int k0 = k0base + src * 4;
                const float* t = g_inputT + (size_t)k0 * BATCH + lane;
                if (mx != 0.0f) accB = fmaf(mx * __ldg(&wb[k0 + 0]), t[0 * BATCH], accB);
                if (my != 0.0f) accB = fmaf(my * __ldg(&wb[k0 + 1]), t[1 * BATCH], accB);
                if (mz != 0.0f) accB = fmaf(mz * __ldg(&wb[k0 + 2]), t[2 * BATCH], accB);
                if (mw != 0.0f) accB = fmaf(mw * __ldg(&wb[k0 + 3]), t[3 * BATCH], accB);
            }
        }
    }

    // epilogue: llr term (pre-scaled, coalesced) + smem transpose, full-sector stores
    __shared__ float tile[16][33];
    tile[warp][lane]     = 0.5f * (g_llrT[(rowA & (N_VAR - 1)) * BATCH + lane] + accA);
    tile[warp + 8][lane] = 0.5f * (g_llrT[(rowB & (N_VAR - 1)) * BATCH + lane] + accB);
    __syncthreads();

    // thread t: b = t>>3 (0..31), el = t&7; each 8-thread group writes two
    // aligned 32B sectors covering out[b][row0 .. row0+15]
    const int b  = threadIdx.x >> 3;
    const int el = threadIdx.x & 7;
    out[(size_t)b * E_EDGE + row0 + el]     = tile[el][b];
    out[(size_t)b * E_EDGE + row0 + 8 + el] = tile[el + 8][b];
}

extern "C" void kernel_launch(void* const* d_in, const int* in_sizes, int n_in,
                              void* d_out, int out_size) {
    const float* input    = (const float*)d_in[0];  // [32, 8192]
    const float* input_w  = (const float*)d_in[1];  // [8192, 8192]
    const float* mask     = (const float*)d_in[2];  // [8192, 8192]
    const float* llr      = (const float*)d_in[3];  // [32, 2048]
    const float* llr_w    = (const float*)d_in[4];  // [1, 2048]
    // d_in[5] = llr_expander (one-hot of e % N_VAR) — realized via index math
    float* out = (float*)d_out;                     // [32, 8192]

    (void)in_sizes; (void)n_in; (void)out_size;

    const int prep_n = E_EDGE * BATCH + N_VAR * BATCH;
    prep_kernel<<<(prep_n + 255) / 256, 256>>>(input, llr, llr_w);

    // 8192 rows, 16 rows (8 warps × 2) per 256-thread block
    bp_main_kernel<<<E_EDGE / 16, 256>>>(mask, input_w, out);
}